// round 6
// baseline (speedup 1.0000x reference)
#include <cuda_runtime.h>

typedef unsigned long long ull;

// Scratch (allocation-free rule: __device__ globals)
__device__ ull g_op0[128 * 16 * 256];  // oproj partial (hp=0): [bt][co2][tok]
__device__ ull g_op1[128 * 16 * 256];  // oproj partial (hp=1)
__device__ float g_hbuf[16 * 32 * 256];// conv output h (b,c,l)
__device__ float g_psum[32 * 128];     // BN partial sums  [c][slot]
__device__ float g_psum2[32 * 128];    // BN partial sumsq
__device__ unsigned g_barrier;         // grid barrier (reset by k_attn)

__device__ __forceinline__ float ex2f(float x) {
    float y;
    asm("ex2.approx.ftz.f32 %0, %1;" : "=f"(y) : "f"(x));
    return y;
}
__device__ __forceinline__ ull pk(float a, float b) {
    ull r; asm("mov.b64 %0, {%1, %2};" : "=l"(r) : "f"(a), "f"(b)); return r;
}
__device__ __forceinline__ void upk(ull x, float& a, float& b) {
    asm("mov.b64 {%0, %1}, %2;" : "=f"(a), "=f"(b) : "l"(x));
}
__device__ __forceinline__ ull fma2(ull a, ull b, ull c) {
    ull r; asm("fma.rn.f32x2 %0, %1, %2, %3;" : "=l"(r) : "l"(a), "l"(b), "l"(c)); return r;
}
__device__ __forceinline__ ull mul2(ull a, ull b) {
    ull r; asm("mul.rn.f32x2 %0, %1, %2;" : "=l"(r) : "l"(a), "l"(b)); return r;
}
__device__ __forceinline__ ull add2(ull a, ull b) {
    ull r; asm("add.rn.f32x2 %0, %1, %2;" : "=l"(r) : "l"(a), "l"(b)); return r;
}
__device__ __forceinline__ float hsum(ull x) {
    float a, b; upk(x, a, b); return a + b;
}

// Software grid barrier (128 co-resident blocks). Counter reset by k_attn.
__device__ __forceinline__ void gbar(unsigned target) {
    __threadfence();
    __syncthreads();
    if (threadIdx.x == 0) {
        atomicAdd(&g_barrier, 1u);
        volatile unsigned* p = &g_barrier;
        while (*p < target) __nanosleep(64);
        __threadfence();
    }
    __syncthreads();
}

// ---------------------------------------------------------------------------
// Kernel A: per (b,t,hp). 4 heads per block. 512 threads = (tok, hgg of 2
// heads). QKV proj -> K/V smem -> attention -> partial oproj (this block's
// 16 channels x all 32 co) -> g_op{hp}. 2 blocks/SM.
// ---------------------------------------------------------------------------
__global__ void __launch_bounds__(512, 2) k_attn(
    const float* __restrict__ x,
    const float* __restrict__ qw, const float* __restrict__ qb,
    const float* __restrict__ kw, const float* __restrict__ kb,
    const float* __restrict__ vw, const float* __restrict__ vb,
    const float* __restrict__ mw)
{
    extern __shared__ float sm[];
    float* kbuf = sm;                  // [4 h][128 mp][8]
    float* vbuf = sm + 4096;
    float* wql = sm + 8192;            // rows hp*16..+15 of q_w
    float* wkl = wql + 512;
    float* wvl = wkl + 512;
    float* wml = wvl + 512;            // m_w[all 32 co][cols hp*16..+15]
    float* bbl = wml + 512;            // [qb16|kb16|vb16]

    const int tid = threadIdx.x;
    const int tok = tid & 255;
    const int hgg = tid >> 8;          // 0 or 1: two heads each
    const int hp = blockIdx.x & 1;     // head group-of-4
    const int t = (blockIdx.x >> 1) & 7;
    const int b = blockIdx.x >> 4;

    if (blockIdx.x == 0 && tid == 0) g_barrier = 0;  // arm k_tail's barrier

    for (int i = tid; i < 512; i += 512) {
        int row = i >> 5, col = i & 31;
        int g = (hp * 16 + row) * 32 + col;
        wql[i] = qw[g]; wkl[i] = kw[g]; wvl[i] = vw[g];
        // m_w sub-block: [co 0..31][local col 0..15]
        int co = i >> 4, cc = i & 15;
        wml[i] = mw[co * 32 + hp * 16 + cc];
    }
    if (tid < 16) {
        bbl[tid] = qb[hp * 16 + tid];
        bbl[16 + tid] = kb[hp * 16 + tid];
        bbl[32 + tid] = vb[hp * 16 + tid];
    }

    float xr[32];
    #pragma unroll
    for (int c = 0; c < 32; c++)
        xr[c] = x[((b * 32 + c) * 16 + t) * 256 + tok];

    __syncthreads();

    ull xp[16];
    #pragma unroll
    for (int i = 0; i < 16; i++) xp[i] = pk(xr[2 * i], xr[2 * i + 1]);

    const ulonglong2* wq2 = (const ulonglong2*)wql;
    const ulonglong2* wk2 = (const ulonglong2*)wkl;
    const ulonglong2* wv2 = (const ulonglong2*)wvl;

    const float QS = 0.5f * 1.4426950408889634f;
    ull qp[4];
    #pragma unroll
    for (int hh = 0; hh < 2; hh++) {
        const int hl = hgg * 2 + hh;   // local head 0..3
        float qv[4], kv[4], vv[4];
        #pragma unroll
        for (int j = 0; j < 4; j++) {
            const int co = hl * 4 + j;
            ull a0 = 0, a1 = 0, b0 = 0, b1 = 0, c0 = 0, c1 = 0;
            #pragma unroll
            for (int c4 = 0; c4 < 8; c4++) {
                ulonglong2 w = wq2[co * 8 + c4];
                a0 = fma2(xp[2 * c4], w.x, a0);
                a1 = fma2(xp[2 * c4 + 1], w.y, a1);
                w = wk2[co * 8 + c4];
                b0 = fma2(xp[2 * c4], w.x, b0);
                b1 = fma2(xp[2 * c4 + 1], w.y, b1);
                w = wv2[co * 8 + c4];
                c0 = fma2(xp[2 * c4], w.x, c0);
                c1 = fma2(xp[2 * c4 + 1], w.y, c1);
            }
            qv[j] = hsum(add2(a0, a1)) + bbl[co];
            kv[j] = hsum(add2(b0, b1)) + bbl[16 + co];
            vv[j] = hsum(add2(c0, c1)) + bbl[32 + co];
        }
        float qn = sqrtf(qv[0]*qv[0] + qv[1]*qv[1] + qv[2]*qv[2] + qv[3]*qv[3]);
        float qi = QS / fmaxf(qn, 1e-12f);
        qp[2 * hh]     = pk(qv[0] * qi, qv[1] * qi);
        qp[2 * hh + 1] = pk(qv[2] * qi, qv[3] * qi);

        float kn = sqrtf(kv[0]*kv[0] + kv[1]*kv[1] + kv[2]*kv[2] + kv[3]*kv[3]);
        float ki = 1.0f / fmaxf(kn, 1e-12f);
        float vn = sqrtf(vv[0]*vv[0] + vv[1]*vv[1] + vv[2]*vv[2] + vv[3]*vv[3]);
        float vi = 1.0f / fmaxf(vn, 1e-12f);

        const int base = hl * 1024 + (tok >> 1) * 8 + (tok & 1);
        #pragma unroll
        for (int d = 0; d < 4; d++) {
            kbuf[base + 2 * d] = kv[d] * ki;
            vbuf[base + 2 * d] = vv[d] * vi;
        }
    }
    __syncthreads();

    ull ov[4];   // this thread's 8 o-channels (2 heads) as 4 pairs
    #pragma unroll
    for (int hh = 0; hh < 2; hh++) {
        const int hl = hgg * 2 + hh;
        const ulonglong2* kb2 = (const ulonglong2*)(kbuf + hl * 1024);
        const ulonglong2* vb2 = (const ulonglong2*)(vbuf + hl * 1024);
        float q0, q1, q2, q3;
        upk(qp[2 * hh], q0, q1); upk(qp[2 * hh + 1], q2, q3);
        const ull Q0 = pk(q0, q0), Q1 = pk(q1, q1), Q2 = pk(q2, q2), Q3 = pk(q3, q3);

        ull pa0 = 0, pa1 = 0, pa2 = 0, pa3 = 0, ss = 0;
        #pragma unroll 4
        for (int mp = 0; mp < 128; mp++) {
            ulonglong2 KA = kb2[2 * mp];
            ulonglong2 KB = kb2[2 * mp + 1];
            ull s = mul2(Q0, KA.x);
            s = fma2(Q1, KA.y, s);
            s = fma2(Q2, KB.x, s);
            s = fma2(Q3, KB.y, s);
            float s0, s1; upk(s, s0, s1);
            ull pp = pk(ex2f(s0), ex2f(s1));
            ulonglong2 VA = vb2[2 * mp];
            ulonglong2 VB = vb2[2 * mp + 1];
            ss = add2(ss, pp);
            pa0 = fma2(pp, VA.x, pa0);
            pa1 = fma2(pp, VA.y, pa1);
            pa2 = fma2(pp, VB.x, pa2);
            pa3 = fma2(pp, VB.y, pa3);
        }
        float inv = 1.0f / hsum(ss);
        ov[2 * hh]     = pk(hsum(pa0) * inv, hsum(pa1) * inv);
        ov[2 * hh + 1] = pk(hsum(pa2) * inv, hsum(pa3) * inv);
    }

    // partial output projection: partial[co] = sum over this thread's 8
    // channels. hgg=0 stages to smem (reusing kbuf/vbuf), hgg=1 adds & STGs.
    __syncthreads();                       // kbuf/vbuf reads done
    ull* posm = (ull*)sm;                  // [16 co2][256 tok]
    const ull* wmu = (const ull*)wml;      // [co][8 pairs]
    const int bt = b * 8 + t;

    if (hgg == 0) {
        #pragma unroll
        for (int co2 = 0; co2 < 16; co2++) {
            ull aA = 0, aB = 0;
            #pragma unroll
            for (int jj = 0; jj < 4; jj++) {
                aA = fma2(ov[jj], wmu[(2 * co2) * 8 + jj], aA);
                aB = fma2(ov[jj], wmu[(2 * co2 + 1) * 8 + jj], aB);
            }
            posm[co2 * 256 + tok] = pk(hsum(aA), hsum(aB));
        }
    }
    __syncthreads();
    if (hgg == 1) {
        ull* dst = hp ? g_op1 : g_op0;
        #pragma unroll
        for (int co2 = 0; co2 < 16; co2++) {
            ull aA = 0, aB = 0;
            #pragma unroll
            for (int jj = 0; jj < 4; jj++) {
                aA = fma2(ov[jj], wmu[(2 * co2) * 8 + 4 + jj], aA);
                aB = fma2(ov[jj], wmu[(2 * co2 + 1) * 8 + 4 + jj], aB);
            }
            dst[(bt * 16 + co2) * 256 + tok] =
                add2(pk(hsum(aA), hsum(aB)), posm[co2 * 256 + tok]);
        }
    }
}

// ---------------------------------------------------------------------------
// Kernel T: fused tail, 128 blocks x 512 threads, ONE grid barrier.
//  ph1: out[:,:,t,:] = op0+op1+mb (block = bt)
//  ph2: conv via smem slab (block = b,tq of 32 toks) + warp BN psums
//  [gbar]  ph3: stats  ph4: BN+ReLU + lin + subtract -> out slot 8
// ---------------------------------------------------------------------------
__global__ void __launch_bounds__(512) k_tail(
    const float* __restrict__ mb, const float* __restrict__ pre,
    const float* __restrict__ cw, const float* __restrict__ cb,
    const float* __restrict__ gamma, const float* __restrict__ beta,
    const float* __restrict__ lw, const float* __restrict__ lb,
    float* __restrict__ out)
{
    extern __shared__ float smd[];
    __shared__ float mbs[32];
    __shared__ float sred[512], sred2[512];
    __shared__ float s_sc[32], s_sh[32];

    const int tid = threadIdx.x;
    const int bid = blockIdx.x;

    if (tid < 32) mbs[tid] = mb[tid];
    __syncthreads();

    // ---- ph1: merge partial oproj -> out slots 0..7 ----
    {
        const int bt = bid, t = bt & 7, b = bt >> 3;
        const int tok = tid & 255, coh = tid >> 8;
        #pragma unroll
        for (int k = 0; k < 8; k++) {
            int co2 = coh * 8 + k;
            ull u = add2(g_op0[(bt * 16 + co2) * 256 + tok],
                         g_op1[(bt * 16 + co2) * 256 + tok]);
            float f0, f1; upk(u, f0, f1);
            int co = 2 * co2;
            out[((b * 32 + co) * 9 + t) * 256 + tok]     = f0 + mbs[co];
            out[((b * 32 + co + 1) * 9 + t) * 256 + tok] = f1 + mbs[co + 1];
        }
    }

    // ---- ph2: conv from smem slab; block = (b = bid>>3, tq = bid&7) ----
    {
        float* slab = smd;            // [288 cikt][32 toks]
        float* cws  = smd + 9216;     // [288 cikt][34] (pad 34 -> ull aligned)
        const int b = bid >> 3, tq = bid & 7;
        const int tok0 = tq * 32;

        for (int idx = tid; idx < 16 * 8 * 32; idx += 512) {
            int co2 = idx >> 8;
            int r = idx & 255;
            int kt = r >> 5, ti2 = r & 31;
            int bt = b * 8 + kt;
            ull u = add2(g_op0[(bt * 16 + co2) * 256 + tok0 + ti2],
                         g_op1[(bt * 16 + co2) * 256 + tok0 + ti2]);
            float f0, f1; upk(u, f0, f1);
            int ci0 = 2 * co2;
            slab[(ci0 * 9 + kt) * 32 + ti2]       = f0 + mbs[ci0];
            slab[((ci0 + 1) * 9 + kt) * 32 + ti2] = f1 + mbs[ci0 + 1];
        }
        for (int idx = tid; idx < 32 * 32; idx += 512) {
            int ci = idx >> 5, ti2 = idx & 31;
            slab[(ci * 9 + 8) * 32 + ti2] = pre[ci * 256 + tok0 + ti2];
        }
        for (int idx = tid; idx < 9216; idx += 512) {
            int co = idx / 288, cikt = idx % 288;
            cws[cikt * 34 + co] = cw[idx];
        }
        __syncthreads();

        const int ti2 = tid & 31, cg = tid >> 5;   // warp = cg (co pair)
        const int co = 2 * cg;
        ull acc = pk(cb[co], cb[co + 1]);
        const ull* cwsu = (const ull*)cws;         // pair at cikt*17 + cg
        #pragma unroll 9
        for (int ckt = 0; ckt < 288; ckt++) {
            float v = slab[ckt * 32 + ti2];
            acc = fma2(pk(v, v), cwsu[ckt * 17 + cg], acc);
        }
        float h0, h1; upk(acc, h0, h1);
        const int gtok = tok0 + ti2;
        g_hbuf[(b * 32 + co) * 256 + gtok]       = h0;
        g_hbuf[(b * 32 + co + 1) * 256 + gtok]   = h1;

        float s0 = h0, q0 = h0 * h0, s1 = h1, q1 = h1 * h1;
        #pragma unroll
        for (int off = 16; off; off >>= 1) {
            s0 += __shfl_down_sync(0xffffffffu, s0, off);
            q0 += __shfl_down_sync(0xffffffffu, q0, off);
            s1 += __shfl_down_sync(0xffffffffu, s1, off);
            q1 += __shfl_down_sync(0xffffffffu, q1, off);
        }
        if (ti2 == 0) {
            g_psum [co * 128 + bid] = s0;  g_psum2[co * 128 + bid] = q0;
            g_psum [(co + 1) * 128 + bid] = s1;  g_psum2[(co + 1) * 128 + bid] = q1;
        }
    }

    gbar(128);

    // ---- ph3: stats (redundant per block, fixed order) ----
    {
        const int co = tid >> 4, part = tid & 15;
        float s = 0.f, s2 = 0.f;
        #pragma unroll
        for (int i = 0; i < 8; i++) {
            s  += g_psum [co * 128 + part * 8 + i];
            s2 += g_psum2[co * 128 + part * 8 + i];
        }
        sred[tid] = s; sred2[tid] = s2;
        __syncthreads();
        if (tid < 32) {
            float S = 0.f, S2 = 0.f;
            #pragma unroll
            for (int p = 0; p < 16; p++) { S += sred[tid * 16 + p]; S2 += sred2[tid * 16 + p]; }
            float mean = S * (1.0f / 4096.0f);
            float var = S2 * (1.0f / 4096.0f) - mean * mean;
            float rstd = rsqrtf(var + 1e-5f);
            float sc = rstd * gamma[tid];
            s_sc[tid] = sc;
            s_sh[tid] = beta[tid] - mean * sc;
        }
        __syncthreads();
    }

    // ---- ph4: BN+ReLU, linear over l, subtract -> out slot 8 ----
    {
        float* hbn = smd;            // [32][256]
        float* lws = smd + 8192;     // [32][260]
        const int lt = bid & 7;
        const int b = bid >> 3;

        for (int idx = tid; idx < 8192; idx += 512) {
            int c = idx >> 8;
            float v = g_hbuf[(b * 32 + c) * 256 + (idx & 255)];
            hbn[idx] = fmaxf(v * s_sc[c] + s_sh[c], 0.f);
        }
        for (int idx = tid; idx < 8192; idx += 512) {
            int r = idx >> 8, col = idx & 255;
            lws[r * 260 + col] = lw[(lt * 32 + r) * 256 + col];
        }
        __syncthreads();

        const int lane = tid & 31, cq = tid >> 5;   // cq in [0,16)
        const int c0 = cq * 2;
        ull acc0 = 0, acc1 = 0;
        const ulonglong2* wrow = (const ulonglong2*)&lws[lane * 260];
        const ulonglong2* h0 = (const ulonglong2*)&hbn[c0 * 256];
        const ulonglong2* h1 = (const ulonglong2*)&hbn[(c0 + 1) * 256];
        #pragma unroll 8
        for (int l4 = 0; l4 < 64; l4++) {
            ulonglong2 w = wrow[l4];
            ulonglong2 a = h0[l4], bq = h1[l4];
            acc0 = fma2(w.x, a.x,  acc0); acc0 = fma2(w.y, a.y,  acc0);
            acc1 = fma2(w.x, bq.x, acc1); acc1 = fma2(w.y, bq.y, acc1);
        }

        const int lp = lt * 32 + lane;
        const float lbv = lb[lp];
        {
            int base0 = (b * 32 + c0) * 9;
            float p0 = hsum(acc0) + lbv;
            out[(base0 + 8) * 256 + lp] = out[(base0 + 2) * 256 + lp] - p0;
            int base1 = (b * 32 + c0 + 1) * 9;
            float p1 = hsum(acc1) + lbv;
            out[(base1 + 8) * 256 + lp] = out[(base1 + 2) * 256 + lp] - p1;
        }
    }
}

// ---------------------------------------------------------------------------
extern "C" void kernel_launch(void* const* d_in, const int* in_sizes, int n_in,
                              void* d_out, int out_size)
{
    const float* x     = (const float*)d_in[0];
    const float* qw    = (const float*)d_in[1];
    const float* qb    = (const float*)d_in[2];
    const float* kw    = (const float*)d_in[3];
    const float* kb    = (const float*)d_in[4];
    const float* vw    = (const float*)d_in[5];
    const float* vb    = (const float*)d_in[6];
    const float* mw    = (const float*)d_in[7];
    const float* mb    = (const float*)d_in[8];
    const float* pre   = (const float*)d_in[9];
    const float* cw    = (const float*)d_in[10];
    const float* cb    = (const float*)d_in[11];
    const float* gamma = (const float*)d_in[12];
    const float* beta  = (const float*)d_in[13];
    const float* lw    = (const float*)d_in[14];
    const float* lb    = (const float*)d_in[15];
    float* out = (float*)d_out;

    const int smemA = (4096 + 4096 + 512 * 4 + 48) * 4;   // 41152 B
    cudaFuncSetAttribute(k_attn, cudaFuncAttributeMaxDynamicSharedMemorySize, smemA);
    const int smemT = (9216 + 288 * 34) * 4;              // 76032 B
    cudaFuncSetAttribute(k_tail, cudaFuncAttributeMaxDynamicSharedMemorySize, smemT);

    k_attn<<<256, 512, smemA>>>(x, qw, qb, kw, kb, vw, vb, mw);
    k_tail<<<128, 512, smemT>>>(mb, pre, cw, cb, gamma, beta, lw, lb, out);
}

// round 7
// speedup vs baseline: 1.0141x; 1.0141x over previous
#include <cuda_runtime.h>

typedef unsigned long long ull;

// Scratch (allocation-free rule: __device__ globals)
__device__ float g_hbuf[16 * 32 * 256];// conv output h (b,c,l)
__device__ float g_psum[32 * 128];     // BN partial sums  [c][slot]
__device__ float g_psum2[32 * 128];    // BN partial sumsq
__device__ unsigned g_barrier;         // grid barrier (reset by k_attn)

__device__ __forceinline__ float ex2f(float x) {
    float y;
    asm("ex2.approx.ftz.f32 %0, %1;" : "=f"(y) : "f"(x));
    return y;
}
__device__ __forceinline__ ull pk(float a, float b) {
    ull r; asm("mov.b64 %0, {%1, %2};" : "=l"(r) : "f"(a), "f"(b)); return r;
}
__device__ __forceinline__ void upk(ull x, float& a, float& b) {
    asm("mov.b64 {%0, %1}, %2;" : "=f"(a), "=f"(b) : "l"(x));
}
__device__ __forceinline__ ull fma2(ull a, ull b, ull c) {
    ull r; asm("fma.rn.f32x2 %0, %1, %2, %3;" : "=l"(r) : "l"(a), "l"(b), "l"(c)); return r;
}
__device__ __forceinline__ ull mul2(ull a, ull b) {
    ull r; asm("mul.rn.f32x2 %0, %1, %2;" : "=l"(r) : "l"(a), "l"(b)); return r;
}
__device__ __forceinline__ ull add2(ull a, ull b) {
    ull r; asm("add.rn.f32x2 %0, %1, %2;" : "=l"(r) : "l"(a), "l"(b)); return r;
}
__device__ __forceinline__ float hsum(ull x) {
    float a, b; upk(x, a, b); return a + b;
}

// Software grid barrier (128 co-resident blocks). Counter reset by k_attn.
__device__ __forceinline__ void gbar(unsigned target) {
    __threadfence();
    __syncthreads();
    if (threadIdx.x == 0) {
        atomicAdd(&g_barrier, 1u);
        volatile unsigned* p = &g_barrier;
        while (*p < target) __nanosleep(64);
        __threadfence();
    }
    __syncthreads();
}

// ---------------------------------------------------------------------------
// Kernel A: per (b,t), ALL 8 heads. 1024 threads = (tok, hgg of 2 heads).
// QKV proj -> K/V smem (d-major m-pair interleaved) -> attention -> o
// exchanged via smem -> full output projection -> out[:, :, t, :].
// grid = 128 blocks, 1 block/SM (32 warps).
// ---------------------------------------------------------------------------
__global__ void __launch_bounds__(1024, 1) k_attn(
    const float* __restrict__ x,
    const float* __restrict__ qw, const float* __restrict__ qb,
    const float* __restrict__ kw, const float* __restrict__ kb,
    const float* __restrict__ vw, const float* __restrict__ vb,
    const float* __restrict__ mw, const float* __restrict__ mb,
    float* __restrict__ out)
{
    extern __shared__ float sm[];
    float* kbuf = sm;                  // [8 h][128 mp][8]
    float* vbuf = sm + 8192;
    float* wq = sm + 16384;            // 1024 each
    float* wk = wq + 1024;
    float* wv = wk + 1024;
    float* wm = wv + 1024;
    float* bb = wm + 1024;             // [qb|kb|vb|mb] 4*32

    const int tid = threadIdx.x;
    const int tok = tid & 255;
    const int hgg = tid >> 8;          // 0..3, two heads each
    const int t = blockIdx.x & 7;
    const int b = blockIdx.x >> 3;

    if (blockIdx.x == 0 && tid == 0) g_barrier = 0;  // arm k_tail's barrier

    if (tid < 1024) {
        wq[tid] = qw[tid]; wk[tid] = kw[tid];
        wv[tid] = vw[tid]; wm[tid] = mw[tid];
    }
    if (tid < 32) {
        bb[tid] = qb[tid]; bb[32 + tid] = kb[tid];
        bb[64 + tid] = vb[tid]; bb[96 + tid] = mb[tid];
    }

    // x[b, c, t, tok] column (coalesced over tok; 4 hgg groups redundant)
    float xr[32];
    #pragma unroll
    for (int c = 0; c < 32; c++)
        xr[c] = x[((b * 32 + c) * 16 + t) * 256 + tok];

    __syncthreads();

    ull xp[16];
    #pragma unroll
    for (int i = 0; i < 16; i++) xp[i] = pk(xr[2 * i], xr[2 * i + 1]);

    const ulonglong2* wq2 = (const ulonglong2*)wq;
    const ulonglong2* wk2 = (const ulonglong2*)wk;
    const ulonglong2* wv2 = (const ulonglong2*)wv;

    const float QS = 0.5f * 1.4426950408889634f;
    ull qp[4];
    #pragma unroll
    for (int hh = 0; hh < 2; hh++) {
        const int h = hgg * 2 + hh;    // global head 0..7
        float qv[4], kv[4], vv[4];
        #pragma unroll
        for (int j = 0; j < 4; j++) {
            const int co = h * 4 + j;
            ull a0 = 0, a1 = 0, b0 = 0, b1 = 0, c0 = 0, c1 = 0;
            #pragma unroll
            for (int c4 = 0; c4 < 8; c4++) {
                ulonglong2 w = wq2[co * 8 + c4];
                a0 = fma2(xp[2 * c4], w.x, a0);
                a1 = fma2(xp[2 * c4 + 1], w.y, a1);
                w = wk2[co * 8 + c4];
                b0 = fma2(xp[2 * c4], w.x, b0);
                b1 = fma2(xp[2 * c4 + 1], w.y, b1);
                w = wv2[co * 8 + c4];
                c0 = fma2(xp[2 * c4], w.x, c0);
                c1 = fma2(xp[2 * c4 + 1], w.y, c1);
            }
            qv[j] = hsum(add2(a0, a1)) + bb[co];
            kv[j] = hsum(add2(b0, b1)) + bb[32 + co];
            vv[j] = hsum(add2(c0, c1)) + bb[64 + co];
        }
        float qn = sqrtf(qv[0]*qv[0] + qv[1]*qv[1] + qv[2]*qv[2] + qv[3]*qv[3]);
        float qi = QS / fmaxf(qn, 1e-12f);
        qp[2 * hh]     = pk(qv[0] * qi, qv[1] * qi);
        qp[2 * hh + 1] = pk(qv[2] * qi, qv[3] * qi);

        float kn = sqrtf(kv[0]*kv[0] + kv[1]*kv[1] + kv[2]*kv[2] + kv[3]*kv[3]);
        float ki = 1.0f / fmaxf(kn, 1e-12f);
        float vn = sqrtf(vv[0]*vv[0] + vv[1]*vv[1] + vv[2]*vv[2] + vv[3]*vv[3]);
        float vi = 1.0f / fmaxf(vn, 1e-12f);

        const int base = h * 1024 + (tok >> 1) * 8 + (tok & 1);
        #pragma unroll
        for (int d = 0; d < 4; d++) {
            kbuf[base + 2 * d] = kv[d] * ki;
            vbuf[base + 2 * d] = vv[d] * vi;
        }
    }
    __syncthreads();

    // attention; scores in [-0.5,0.5] -> exp2, no max pass.
    ull ov[4];   // this thread's 8 o-channels (2 heads) as 4 pairs
    #pragma unroll
    for (int hh = 0; hh < 2; hh++) {
        const int h = hgg * 2 + hh;
        const ulonglong2* kb2 = (const ulonglong2*)(kbuf + h * 1024);
        const ulonglong2* vb2 = (const ulonglong2*)(vbuf + h * 1024);
        float q0, q1, q2, q3;
        upk(qp[2 * hh], q0, q1); upk(qp[2 * hh + 1], q2, q3);
        const ull Q0 = pk(q0, q0), Q1 = pk(q1, q1), Q2 = pk(q2, q2), Q3 = pk(q3, q3);

        ull pa0 = 0, pa1 = 0, pa2 = 0, pa3 = 0, ss = 0;
        #pragma unroll 4
        for (int mp = 0; mp < 128; mp++) {
            ulonglong2 KA = kb2[2 * mp];
            ulonglong2 KB = kb2[2 * mp + 1];
            ull s = mul2(Q0, KA.x);
            s = fma2(Q1, KA.y, s);
            s = fma2(Q2, KB.x, s);
            s = fma2(Q3, KB.y, s);
            float s0, s1; upk(s, s0, s1);
            ull pp = pk(ex2f(s0), ex2f(s1));
            ulonglong2 VA = vb2[2 * mp];
            ulonglong2 VB = vb2[2 * mp + 1];
            ss = add2(ss, pp);
            pa0 = fma2(pp, VA.x, pa0);
            pa1 = fma2(pp, VA.y, pa1);
            pa2 = fma2(pp, VB.x, pa2);
            pa3 = fma2(pp, VB.y, pa3);
        }
        float inv = 1.0f / hsum(ss);
        ov[2 * hh]     = pk(hsum(pa0) * inv, hsum(pa1) * inv);
        ov[2 * hh + 1] = pk(hsum(pa2) * inv, hsum(pa3) * inv);
    }

    // exchange o through smem (recycle kbuf/vbuf), then full out projection
    __syncthreads();                       // kbuf/vbuf reads done
    ull* osm = (ull*)sm;                   // [256 tok][17] ull (16 used)
    #pragma unroll
    for (int u = 0; u < 4; u++)
        osm[tok * 17 + hgg * 4 + u] = ov[u];   // channel pair c2 = hgg*4+u
    __syncthreads();

    ull ovv[16];
    #pragma unroll
    for (int i = 0; i < 16; i++) ovv[i] = osm[tok * 17 + i];

    const ull* wmu = (const ull*)wm;       // row co: 16 ull (warp-uniform)
    #pragma unroll
    for (int j = 0; j < 8; j++) {
        const int co = hgg * 8 + j;
        ull a0 = 0, a1 = 0;
        #pragma unroll
        for (int i = 0; i < 16; i += 2) {
            a0 = fma2(ovv[i],     wmu[co * 16 + i],     a0);
            a1 = fma2(ovv[i + 1], wmu[co * 16 + i + 1], a1);
        }
        out[((b * 32 + co) * 9 + t) * 256 + tok] = hsum(add2(a0, a1)) + bb[96 + co];
    }
}

// ---------------------------------------------------------------------------
// Kernel T: tail, 128 blocks x 512 threads, ONE grid barrier.
//  ph1: conv via smem slab read from out (block = b, tq of 32 toks) + psums
//  [gbar]  ph2: stats (redundant, fixed order)  ph3: BN+ReLU + lin + subtract
// ---------------------------------------------------------------------------
__global__ void __launch_bounds__(512) k_tail(
    const float* __restrict__ pre,
    const float* __restrict__ cw, const float* __restrict__ cb,
    const float* __restrict__ gamma, const float* __restrict__ beta,
    const float* __restrict__ lw, const float* __restrict__ lb,
    float* __restrict__ out)
{
    extern __shared__ float smd[];
    __shared__ float sred[512], sred2[512];
    __shared__ float s_sc[32], s_sh[32];

    const int tid = threadIdx.x;
    const int bid = blockIdx.x;

    // ---- ph1: conv from smem slab; block = (b = bid>>3, tq = bid&7) ----
    {
        float* slab = smd;            // [288 cikt][32 toks]
        float* cws  = smd + 9216;     // [288 cikt][34] (pad 34 -> ull aligned)
        const int b = bid >> 3, tq = bid & 7;
        const int tok0 = tq * 32;

        for (int idx = tid; idx < 9216; idx += 512) {
            int cikt = idx >> 5, ti2 = idx & 31;
            int ci = cikt / 9, kt = cikt - ci * 9;
            float v = (kt < 8) ? out[((b * 32 + ci) * 9 + kt) * 256 + tok0 + ti2]
                               : pre[ci * 256 + tok0 + ti2];
            slab[cikt * 32 + ti2] = v;
        }
        for (int idx = tid; idx < 9216; idx += 512) {
            int co = idx / 288, cikt = idx - co * 288;
            cws[cikt * 34 + co] = cw[idx];
        }
        __syncthreads();

        const int ti2 = tid & 31, cg = tid >> 5;   // warp = cg (co pair)
        const int co = 2 * cg;
        ull acc = pk(cb[co], cb[co + 1]);
        const ull* cwsu = (const ull*)cws;         // pair at cikt*17 + cg
        #pragma unroll 9
        for (int ckt = 0; ckt < 288; ckt++) {
            float v = slab[ckt * 32 + ti2];
            acc = fma2(pk(v, v), cwsu[ckt * 17 + cg], acc);
        }
        float h0, h1; upk(acc, h0, h1);
        const int gtok = tok0 + ti2;
        g_hbuf[(b * 32 + co) * 256 + gtok]       = h0;
        g_hbuf[(b * 32 + co + 1) * 256 + gtok]   = h1;

        float s0 = h0, q0 = h0 * h0, s1 = h1, q1 = h1 * h1;
        #pragma unroll
        for (int off = 16; off; off >>= 1) {
            s0 += __shfl_down_sync(0xffffffffu, s0, off);
            q0 += __shfl_down_sync(0xffffffffu, q0, off);
            s1 += __shfl_down_sync(0xffffffffu, s1, off);
            q1 += __shfl_down_sync(0xffffffffu, q1, off);
        }
        if (ti2 == 0) {
            g_psum [co * 128 + bid] = s0;  g_psum2[co * 128 + bid] = q0;
            g_psum [(co + 1) * 128 + bid] = s1;  g_psum2[(co + 1) * 128 + bid] = q1;
        }
    }

    gbar(128);

    // ---- ph2: stats (redundant per block, fixed order) ----
    {
        const int co = tid >> 4, part = tid & 15;
        float s = 0.f, s2 = 0.f;
        #pragma unroll
        for (int i = 0; i < 8; i++) {
            s  += g_psum [co * 128 + part * 8 + i];
            s2 += g_psum2[co * 128 + part * 8 + i];
        }
        sred[tid] = s; sred2[tid] = s2;
        __syncthreads();
        if (tid < 32) {
            float S = 0.f, S2 = 0.f;
            #pragma unroll
            for (int p = 0; p < 16; p++) { S += sred[tid * 16 + p]; S2 += sred2[tid * 16 + p]; }
            float mean = S * (1.0f / 4096.0f);
            float var = S2 * (1.0f / 4096.0f) - mean * mean;
            float rstd = rsqrtf(var + 1e-5f);
            float sc = rstd * gamma[tid];
            s_sc[tid] = sc;
            s_sh[tid] = beta[tid] - mean * sc;
        }
        __syncthreads();
    }

    // ---- ph3: BN+ReLU, linear over l, subtract -> out slot 8 ----
    {
        float* hbn = smd;            // [32][256]
        float* lws = smd + 8192;     // [32][260]
        const int lt = bid & 7;
        const int b = bid >> 3;

        for (int idx = tid; idx < 8192; idx += 512) {
            int c = idx >> 8;
            float v = g_hbuf[(b * 32 + c) * 256 + (idx & 255)];
            hbn[idx] = fmaxf(v * s_sc[c] + s_sh[c], 0.f);
        }
        for (int idx = tid; idx < 8192; idx += 512) {
            int r = idx >> 8, col = idx & 255;
            lws[r * 260 + col] = lw[(lt * 32 + r) * 256 + col];
        }
        __syncthreads();

        const int lane = tid & 31, cq = tid >> 5;   // cq in [0,16)
        const int c0 = cq * 2;
        ull acc0 = 0, acc1 = 0;
        const ulonglong2* wrow = (const ulonglong2*)&lws[lane * 260];
        const ulonglong2* h0 = (const ulonglong2*)&hbn[c0 * 256];
        const ulonglong2* h1 = (const ulonglong2*)&hbn[(c0 + 1) * 256];
        #pragma unroll 8
        for (int l4 = 0; l4 < 64; l4++) {
            ulonglong2 w = wrow[l4];
            ulonglong2 a = h0[l4], bq = h1[l4];
            acc0 = fma2(w.x, a.x,  acc0); acc0 = fma2(w.y, a.y,  acc0);
            acc1 = fma2(w.x, bq.x, acc1); acc1 = fma2(w.y, bq.y, acc1);
        }

        const int lp = lt * 32 + lane;
        const float lbv = lb[lp];
        {
            int base0 = (b * 32 + c0) * 9;
            float p0 = hsum(acc0) + lbv;
            out[(base0 + 8) * 256 + lp] = out[(base0 + 2) * 256 + lp] - p0;
            int base1 = (b * 32 + c0 + 1) * 9;
            float p1 = hsum(acc1) + lbv;
            out[(base1 + 8) * 256 + lp] = out[(base1 + 2) * 256 + lp] - p1;
        }
    }
}

// ---------------------------------------------------------------------------
extern "C" void kernel_launch(void* const* d_in, const int* in_sizes, int n_in,
                              void* d_out, int out_size)
{
    const float* x     = (const float*)d_in[0];
    const float* qw    = (const float*)d_in[1];
    const float* qb    = (const float*)d_in[2];
    const float* kw    = (const float*)d_in[3];
    const float* kb    = (const float*)d_in[4];
    const float* vw    = (const float*)d_in[5];
    const float* vb    = (const float*)d_in[6];
    const float* mw    = (const float*)d_in[7];
    const float* mb    = (const float*)d_in[8];
    const float* pre   = (const float*)d_in[9];
    const float* cw    = (const float*)d_in[10];
    const float* cb    = (const float*)d_in[11];
    const float* gamma = (const float*)d_in[12];
    const float* beta  = (const float*)d_in[13];
    const float* lw    = (const float*)d_in[14];
    const float* lb    = (const float*)d_in[15];
    float* out = (float*)d_out;

    const int smemA = (8192 + 8192 + 4096 + 128) * 4;   // 82432 B
    cudaFuncSetAttribute(k_attn, cudaFuncAttributeMaxDynamicSharedMemorySize, smemA);
    const int smemT = (9216 + 288 * 34) * 4;            // 76032 B
    cudaFuncSetAttribute(k_tail, cudaFuncAttributeMaxDynamicSharedMemorySize, smemT);

    k_attn<<<128, 1024, smemA>>>(x, qw, qb, kw, kb, vw, vb, mw, mb, out);
    k_tail<<<128, 512, smemT>>>(pre, cw, cb, gamma, beta, lw, lb, out);
}

// round 8
// speedup vs baseline: 1.1244x; 1.1088x over previous
#include <cuda_runtime.h>

typedef unsigned long long ull;

// Scratch (allocation-free rule: __device__ globals; zero-initialized)
__device__ float g_hbuf[16 * 32 * 256];  // conv output h (b,c,l)
__device__ float g_psum[32 * 128];       // BN partial sums  [c][slot]
__device__ float g_psum2[32 * 128];      // BN partial sumsq
__device__ unsigned g_bar1, g_bar2, g_fin;

__device__ __forceinline__ float ex2f(float x) {
    float y;
    asm("ex2.approx.ftz.f32 %0, %1;" : "=f"(y) : "f"(x));
    return y;
}
__device__ __forceinline__ ull pk(float a, float b) {
    ull r; asm("mov.b64 %0, {%1, %2};" : "=l"(r) : "f"(a), "f"(b)); return r;
}
__device__ __forceinline__ void upk(ull x, float& a, float& b) {
    asm("mov.b64 {%0, %1}, %2;" : "=f"(a), "=f"(b) : "l"(x));
}
__device__ __forceinline__ ull fma2(ull a, ull b, ull c) {
    ull r; asm("fma.rn.f32x2 %0, %1, %2, %3;" : "=l"(r) : "l"(a), "l"(b), "l"(c)); return r;
}
__device__ __forceinline__ ull mul2(ull a, ull b) {
    ull r; asm("mul.rn.f32x2 %0, %1, %2;" : "=l"(r) : "l"(a), "l"(b)); return r;
}
__device__ __forceinline__ ull add2(ull a, ull b) {
    ull r; asm("add.rn.f32x2 %0, %1, %2;" : "=l"(r) : "l"(a), "l"(b)); return r;
}
__device__ __forceinline__ float hsum(ull x) {
    float a, b; upk(x, a, b); return a + b;
}

// Grid barrier over 128 co-resident blocks (one wave on 148 SMs).
__device__ __forceinline__ void gbar(unsigned* ctr) {
    __threadfence();
    __syncthreads();
    if (threadIdx.x == 0) {
        atomicAdd(ctr, 1u);
        volatile unsigned* p = ctr;
        while (*p < 128u) __nanosleep(32);
        __threadfence();
    }
    __syncthreads();
}

// ---------------------------------------------------------------------------
// ONE persistent kernel. 128 blocks x 1024 threads (32 warps/SM).
//  Phase A: per (b,t) = bid: QKV proj + l2norm + attention + out proj
//           -> out[:, :, t, :]                     (thread = tok x hgg)
//  [gbar1]
//  Phase B: conv(9,1)+bias for (b=bid>>3, 32 toks) split-K over warp pairs
//           -> g_hbuf + BN partial sums
//  [gbar2]
//  Phase C: BN stats (redundant per block, fixed order)
//  Phase D: BN+ReLU + linear over l + subtract -> out slot 8
//  Epilogue: last block resets barrier counters (graph-replay safe).
// ---------------------------------------------------------------------------
__global__ void __launch_bounds__(1024, 1) k_fused(
    const float* __restrict__ x,
    const float* __restrict__ qw, const float* __restrict__ qb,
    const float* __restrict__ kw, const float* __restrict__ kb,
    const float* __restrict__ vw, const float* __restrict__ vb,
    const float* __restrict__ mw, const float* __restrict__ mb,
    const float* __restrict__ pre,
    const float* __restrict__ cw, const float* __restrict__ cb,
    const float* __restrict__ gamma, const float* __restrict__ beta,
    const float* __restrict__ lw, const float* __restrict__ lb,
    float* __restrict__ out)
{
    extern __shared__ float sm[];
    __shared__ float s_sc[32], s_sh[32];

    const int tid = threadIdx.x;
    const int bid = blockIdx.x;

    // ======================= Phase A: attention ============================
    {
        float* kbuf = sm;                  // [8 h][128 mp][8]
        float* vbuf = sm + 8192;
        float* wq = sm + 16384;            // 1024 each
        float* wk = wq + 1024;
        float* wv = wk + 1024;
        float* wm = wv + 1024;
        float* bb = wm + 1024;             // [qb|kb|vb|mb]

        const int tok = tid & 255;
        const int hgg = tid >> 8;          // 0..3, two heads each
        const int t = bid & 7;
        const int b = bid >> 3;

        wq[tid] = qw[tid]; wk[tid] = kw[tid];
        wv[tid] = vw[tid]; wm[tid] = mw[tid];
        if (tid < 32) {
            bb[tid] = qb[tid]; bb[32 + tid] = kb[tid];
            bb[64 + tid] = vb[tid]; bb[96 + tid] = mb[tid];
        }

        float xr[32];
        #pragma unroll
        for (int c = 0; c < 32; c++)
            xr[c] = x[((b * 32 + c) * 16 + t) * 256 + tok];

        __syncthreads();

        ull xp[16];
        #pragma unroll
        for (int i = 0; i < 16; i++) xp[i] = pk(xr[2 * i], xr[2 * i + 1]);

        const ulonglong2* wq2 = (const ulonglong2*)wq;
        const ulonglong2* wk2 = (const ulonglong2*)wk;
        const ulonglong2* wv2 = (const ulonglong2*)wv;

        const float QS = 0.5f * 1.4426950408889634f;
        ull qp[4];
        #pragma unroll
        for (int hh = 0; hh < 2; hh++) {
            const int h = hgg * 2 + hh;
            float qv[4], kv[4], vv[4];
            #pragma unroll
            for (int j = 0; j < 4; j++) {
                const int co = h * 4 + j;
                ull a0 = 0, a1 = 0, b0 = 0, b1 = 0, c0 = 0, c1 = 0;
                #pragma unroll
                for (int c4 = 0; c4 < 8; c4++) {
                    ulonglong2 w = wq2[co * 8 + c4];
                    a0 = fma2(xp[2 * c4], w.x, a0);
                    a1 = fma2(xp[2 * c4 + 1], w.y, a1);
                    w = wk2[co * 8 + c4];
                    b0 = fma2(xp[2 * c4], w.x, b0);
                    b1 = fma2(xp[2 * c4 + 1], w.y, b1);
                    w = wv2[co * 8 + c4];
                    c0 = fma2(xp[2 * c4], w.x, c0);
                    c1 = fma2(xp[2 * c4 + 1], w.y, c1);
                }
                qv[j] = hsum(add2(a0, a1)) + bb[co];
                kv[j] = hsum(add2(b0, b1)) + bb[32 + co];
                vv[j] = hsum(add2(c0, c1)) + bb[64 + co];
            }
            float qn = sqrtf(qv[0]*qv[0] + qv[1]*qv[1] + qv[2]*qv[2] + qv[3]*qv[3]);
            float qi = QS / fmaxf(qn, 1e-12f);
            qp[2 * hh]     = pk(qv[0] * qi, qv[1] * qi);
            qp[2 * hh + 1] = pk(qv[2] * qi, qv[3] * qi);

            float kn = sqrtf(kv[0]*kv[0] + kv[1]*kv[1] + kv[2]*kv[2] + kv[3]*kv[3]);
            float ki = 1.0f / fmaxf(kn, 1e-12f);
            float vn = sqrtf(vv[0]*vv[0] + vv[1]*vv[1] + vv[2]*vv[2] + vv[3]*vv[3]);
            float vi = 1.0f / fmaxf(vn, 1e-12f);

            const int base = h * 1024 + (tok >> 1) * 8 + (tok & 1);
            #pragma unroll
            for (int d = 0; d < 4; d++) {
                kbuf[base + 2 * d] = kv[d] * ki;
                vbuf[base + 2 * d] = vv[d] * vi;
            }
        }
        __syncthreads();

        ull ov[4];
        #pragma unroll
        for (int hh = 0; hh < 2; hh++) {
            const int h = hgg * 2 + hh;
            const ulonglong2* kb2 = (const ulonglong2*)(kbuf + h * 1024);
            const ulonglong2* vb2 = (const ulonglong2*)(vbuf + h * 1024);
            float q0, q1, q2, q3;
            upk(qp[2 * hh], q0, q1); upk(qp[2 * hh + 1], q2, q3);
            const ull Q0 = pk(q0, q0), Q1 = pk(q1, q1), Q2 = pk(q2, q2), Q3 = pk(q3, q3);

            ull pa0 = 0, pa1 = 0, pa2 = 0, pa3 = 0, ss = 0;
            #pragma unroll 4
            for (int mp = 0; mp < 128; mp++) {
                ulonglong2 KA = kb2[2 * mp];
                ulonglong2 KB = kb2[2 * mp + 1];
                ull s = mul2(Q0, KA.x);
                s = fma2(Q1, KA.y, s);
                s = fma2(Q2, KB.x, s);
                s = fma2(Q3, KB.y, s);
                float s0, s1; upk(s, s0, s1);
                ull pp = pk(ex2f(s0), ex2f(s1));
                ulonglong2 VA = vb2[2 * mp];
                ulonglong2 VB = vb2[2 * mp + 1];
                ss = add2(ss, pp);
                pa0 = fma2(pp, VA.x, pa0);
                pa1 = fma2(pp, VA.y, pa1);
                pa2 = fma2(pp, VB.x, pa2);
                pa3 = fma2(pp, VB.y, pa3);
            }
            float inv = 1.0f / hsum(ss);
            ov[2 * hh]     = pk(hsum(pa0) * inv, hsum(pa1) * inv);
            ov[2 * hh + 1] = pk(hsum(pa2) * inv, hsum(pa3) * inv);
        }

        // exchange o via smem (recycle kbuf), full out projection
        __syncthreads();
        ull* osm = (ull*)sm;                   // [256 tok][17] ull
        #pragma unroll
        for (int u = 0; u < 4; u++)
            osm[tok * 17 + hgg * 4 + u] = ov[u];
        __syncthreads();

        ull ovv[16];
        #pragma unroll
        for (int i = 0; i < 16; i++) ovv[i] = osm[tok * 17 + i];

        const ull* wmu = (const ull*)wm;
        #pragma unroll
        for (int j = 0; j < 8; j++) {
            const int co = hgg * 8 + j;
            ull a0 = 0, a1 = 0;
            #pragma unroll
            for (int i = 0; i < 16; i += 2) {
                a0 = fma2(ovv[i],     wmu[co * 16 + i],     a0);
                a1 = fma2(ovv[i + 1], wmu[co * 16 + i + 1], a1);
            }
            out[((b * 32 + co) * 9 + t) * 256 + tok] = hsum(add2(a0, a1)) + bb[96 + co];
        }
    }

    gbar(&g_bar1);

    // ======================= Phase B: conv + psums =========================
    {
        float* slab = sm;                  // [288 cikt][32 toks]
        float* cws  = sm + 9216;           // [288 cikt][34]
        ull*   psmem = (ull*)(sm + 19008); // [16 cg][32]
        const int b = bid >> 3, tq = bid & 7;
        const int tok0 = tq * 32;

        #pragma unroll
        for (int idx = tid; idx < 9216; idx += 1024) {
            int cikt = idx >> 5, ti2 = idx & 31;
            int ci = cikt / 9, kt = cikt - ci * 9;
            float v = (kt < 8) ? out[((b * 32 + ci) * 9 + kt) * 256 + tok0 + ti2]
                               : pre[ci * 256 + tok0 + ti2];
            slab[idx] = v;
        }
        #pragma unroll
        for (int idx = tid; idx < 9216; idx += 1024) {
            int co = idx / 288, cikt = idx - co * 288;
            cws[cikt * 34 + co] = cw[idx];
        }
        __syncthreads();

        const int w = tid >> 5, lane = tid & 31;
        const int cg = w >> 1, half = w & 1, co = 2 * cg;
        ull acc = (half == 0) ? pk(cb[co], cb[co + 1]) : 0ull;
        const ull* cwsu = (const ull*)cws;
        const int k0 = half * 144;
        #pragma unroll 9
        for (int ckt = k0; ckt < k0 + 144; ckt++) {
            float v = slab[ckt * 32 + lane];
            acc = fma2(pk(v, v), cwsu[ckt * 17 + cg], acc);
        }
        if (half == 1) psmem[cg * 32 + lane] = acc;
        __syncthreads();
        if (half == 0) {
            acc = add2(acc, psmem[cg * 32 + lane]);
            float h0, h1; upk(acc, h0, h1);
            const int gtok = tok0 + lane;
            g_hbuf[(b * 32 + co) * 256 + gtok]     = h0;
            g_hbuf[(b * 32 + co + 1) * 256 + gtok] = h1;

            float s0 = h0, q0 = h0 * h0, s1 = h1, q1 = h1 * h1;
            #pragma unroll
            for (int off = 16; off; off >>= 1) {
                s0 += __shfl_down_sync(0xffffffffu, s0, off);
                q0 += __shfl_down_sync(0xffffffffu, q0, off);
                s1 += __shfl_down_sync(0xffffffffu, s1, off);
                q1 += __shfl_down_sync(0xffffffffu, q1, off);
            }
            if (lane == 0) {
                g_psum [co * 128 + bid] = s0;        g_psum2[co * 128 + bid] = q0;
                g_psum [(co + 1) * 128 + bid] = s1;  g_psum2[(co + 1) * 128 + bid] = q1;
            }
        }
    }

    gbar(&g_bar2);

    // ======================= Phase C: BN stats =============================
    {
        float* sred  = sm;           // [32 co][32 part]
        float* sred2 = sm + 1024;
        const int co = tid >> 5, part = tid & 31;
        float s = 0.f, s2 = 0.f;
        #pragma unroll
        for (int i = 0; i < 4; i++) {
            s  += g_psum [co * 128 + part * 4 + i];
            s2 += g_psum2[co * 128 + part * 4 + i];
        }
        sred[co * 32 + part] = s; sred2[co * 32 + part] = s2;
        __syncthreads();
        if (tid < 32) {
            float S = 0.f, S2 = 0.f;
            #pragma unroll
            for (int p = 0; p < 32; p++) { S += sred[tid * 32 + p]; S2 += sred2[tid * 32 + p]; }
            float mean = S * (1.0f / 4096.0f);
            float var = S2 * (1.0f / 4096.0f) - mean * mean;
            float rstd = rsqrtf(var + 1e-5f);
            float sc = rstd * gamma[tid];
            s_sc[tid] = sc;
            s_sh[tid] = beta[tid] - mean * sc;
        }
        __syncthreads();
    }

    // ======================= Phase D: BN+ReLU + linear =====================
    {
        float* hbn = sm;             // [32][256]
        float* lws = sm + 8192;      // [32][260]
        const int lt = bid & 7;
        const int b = bid >> 3;

        #pragma unroll
        for (int idx = tid; idx < 8192; idx += 1024) {
            int c = idx >> 8;
            float v = g_hbuf[(b * 32 + c) * 256 + (idx & 255)];
            hbn[idx] = fmaxf(v * s_sc[c] + s_sh[c], 0.f);
        }
        #pragma unroll
        for (int idx = tid; idx < 8192; idx += 1024) {
            int r = idx >> 8, col = idx & 255;
            lws[r * 260 + col] = lw[(lt * 32 + r) * 256 + col];
        }
        __syncthreads();

        const int lane = tid & 31, cq = tid >> 5;   // cq = channel 0..31
        ull acc0 = 0;
        const ulonglong2* wrow = (const ulonglong2*)&lws[lane * 260];
        const ulonglong2* h0 = (const ulonglong2*)&hbn[cq * 256];
        #pragma unroll 8
        for (int l4 = 0; l4 < 64; l4++) {
            ulonglong2 w = wrow[l4];
            ulonglong2 a = h0[l4];
            acc0 = fma2(w.x, a.x, acc0);
            acc0 = fma2(w.y, a.y, acc0);
        }

        const int lp = lt * 32 + lane;
        float p = hsum(acc0) + lb[lp];
        int base = (b * 32 + cq) * 9;
        out[(base + 8) * 256 + lp] = out[(base + 2) * 256 + lp] - p;
    }

    // ---- epilogue: last block resets barrier counters for next launch ----
    __syncthreads();
    if (tid == 0) {
        unsigned old = atomicAdd(&g_fin, 1u);
        if (old == 127u) {
            atomicExch(&g_bar1, 0u);
            atomicExch(&g_bar2, 0u);
            atomicExch(&g_fin, 0u);
        }
    }
}

// ---------------------------------------------------------------------------
extern "C" void kernel_launch(void* const* d_in, const int* in_sizes, int n_in,
                              void* d_out, int out_size)
{
    const float* x     = (const float*)d_in[0];
    const float* qw    = (const float*)d_in[1];
    const float* qb    = (const float*)d_in[2];
    const float* kw    = (const float*)d_in[3];
    const float* kb    = (const float*)d_in[4];
    const float* vw    = (const float*)d_in[5];
    const float* vb    = (const float*)d_in[6];
    const float* mw    = (const float*)d_in[7];
    const float* mb    = (const float*)d_in[8];
    const float* pre   = (const float*)d_in[9];
    const float* cw    = (const float*)d_in[10];
    const float* cb    = (const float*)d_in[11];
    const float* gamma = (const float*)d_in[12];
    const float* beta  = (const float*)d_in[13];
    const float* lw    = (const float*)d_in[14];
    const float* lb    = (const float*)d_in[15];
    float* out = (float*)d_out;

    const int smem = (8192 + 8192 + 4096 + 128) * 4;   // 82432 B
    cudaFuncSetAttribute(k_fused, cudaFuncAttributeMaxDynamicSharedMemorySize, smem);

    k_fused<<<128, 1024, smem>>>(x, qw, qb, kw, kb, vw, vb, mw, mb,
                                 pre, cw, cb, gamma, beta, lw, lb, out);
}

// round 9
// speedup vs baseline: 1.1888x; 1.0573x over previous
#include <cuda_runtime.h>

typedef unsigned long long ull;

// Scratch (allocation-free rule: __device__ globals; zero-initialized)
__device__ float g_hbuf[16 * 32 * 256];  // conv output h (b,c,l)
__device__ float g_psum[32 * 128];       // BN partial sums  [c][slot]
__device__ float g_psum2[32 * 128];      // BN partial sumsq
__device__ unsigned g_bar1, g_bar2, g_fin;

__device__ __forceinline__ float ex2f(float x) {
    float y;
    asm("ex2.approx.ftz.f32 %0, %1;" : "=f"(y) : "f"(x));
    return y;
}
__device__ __forceinline__ ull pk(float a, float b) {
    ull r; asm("mov.b64 %0, {%1, %2};" : "=l"(r) : "f"(a), "f"(b)); return r;
}
__device__ __forceinline__ void upk(ull x, float& a, float& b) {
    asm("mov.b64 {%0, %1}, %2;" : "=f"(a), "=f"(b) : "l"(x));
}
__device__ __forceinline__ ull fma2(ull a, ull b, ull c) {
    ull r; asm("fma.rn.f32x2 %0, %1, %2, %3;" : "=l"(r) : "l"(a), "l"(b), "l"(c)); return r;
}
__device__ __forceinline__ ull mul2(ull a, ull b) {
    ull r; asm("mul.rn.f32x2 %0, %1, %2;" : "=l"(r) : "l"(a), "l"(b)); return r;
}
__device__ __forceinline__ ull add2(ull a, ull b) {
    ull r; asm("add.rn.f32x2 %0, %1, %2;" : "=l"(r) : "l"(a), "l"(b)); return r;
}
__device__ __forceinline__ float hsum(ull x) {
    float a, b; upk(x, a, b); return a + b;
}

// Grid barrier over 128 co-resident blocks (one wave on 148 SMs).
__device__ __forceinline__ void gbar(unsigned* ctr) {
    __threadfence();
    __syncthreads();
    if (threadIdx.x == 0) {
        atomicAdd(ctr, 1u);
        volatile unsigned* p = ctr;
        while (*p < 128u) __nanosleep(32);
        __threadfence();
    }
    __syncthreads();
}

// ---------------------------------------------------------------------------
// ONE persistent kernel. 128 blocks x 1024 threads (32 warps/SM).
//  Phase A1: QKV proj + l2norm, thread=(tok, hgg of 2 heads); q -> qbuf,
//            k/v -> kbuf/vbuf (d-major m-pair interleaved).
//  Phase A2: attention, thread=(head, token-pair) -> warp serves ONE head ->
//            4 LDS.128 per m-pair (halved smem traffic). o -> osm.
//  Phase A3: out projection, thread=(tok, cog) -> out[:, :, t, :].
//  [gbar1]  Phase B: conv + BN psums   [gbar2]  Phase C: stats
//  Phase D: BN+ReLU + linear + subtract -> out slot 8. Epilogue resets ctrs.
// ---------------------------------------------------------------------------
__global__ void __launch_bounds__(1024, 1) k_fused(
    const float* __restrict__ x,
    const float* __restrict__ qw, const float* __restrict__ qb,
    const float* __restrict__ kw, const float* __restrict__ kb,
    const float* __restrict__ vw, const float* __restrict__ vb,
    const float* __restrict__ mw, const float* __restrict__ mb,
    const float* __restrict__ pre,
    const float* __restrict__ cw, const float* __restrict__ cb,
    const float* __restrict__ gamma, const float* __restrict__ beta,
    const float* __restrict__ lw, const float* __restrict__ lb,
    float* __restrict__ out)
{
    extern __shared__ float sm[];
    __shared__ float s_sc[32], s_sh[32];

    const int tid = threadIdx.x;
    const int bid = blockIdx.x;
    const int t = bid & 7;
    const int b = bid >> 3;

    // Phase A smem map
    float* kbuf = sm;                  // [8 h][128 mp][8]  (8192)
    float* vbuf = sm + 8192;           // 8192
    float* qbuf = sm + 16384;          // [8 h][256 tok][4] (8192)
    float* wq = sm + 24576;            // 1024 each
    float* wk = wq + 1024;
    float* wv = wk + 1024;
    float* wm = wv + 1024;
    float* bb = wm + 1024;             // [qb|kb|vb|mb]

    // =================== Phase A1: QKV proj + l2norm =======================
    {
        const int tok = tid & 255;
        const int hgg = tid >> 8;          // 0..3, two heads each

        wq[tid] = qw[tid]; wk[tid] = kw[tid];
        wv[tid] = vw[tid]; wm[tid] = mw[tid];
        if (tid < 32) {
            bb[tid] = qb[tid]; bb[32 + tid] = kb[tid];
            bb[64 + tid] = vb[tid]; bb[96 + tid] = mb[tid];
        }

        float xr[32];
        #pragma unroll
        for (int c = 0; c < 32; c++)
            xr[c] = x[((b * 32 + c) * 16 + t) * 256 + tok];

        __syncthreads();

        ull xp[16];
        #pragma unroll
        for (int i = 0; i < 16; i++) xp[i] = pk(xr[2 * i], xr[2 * i + 1]);

        const ulonglong2* wq2 = (const ulonglong2*)wq;
        const ulonglong2* wk2 = (const ulonglong2*)wk;
        const ulonglong2* wv2 = (const ulonglong2*)wv;

        const float QS = 0.5f * 1.4426950408889634f;  // (1/sqrt(hd))*log2(e)
        #pragma unroll
        for (int hh = 0; hh < 2; hh++) {
            const int h = hgg * 2 + hh;
            float qv[4], kv[4], vv[4];
            #pragma unroll
            for (int j = 0; j < 4; j++) {
                const int co = h * 4 + j;
                ull a0 = 0, a1 = 0, b0 = 0, b1 = 0, c0 = 0, c1 = 0;
                #pragma unroll
                for (int c4 = 0; c4 < 8; c4++) {
                    ulonglong2 w = wq2[co * 8 + c4];
                    a0 = fma2(xp[2 * c4], w.x, a0);
                    a1 = fma2(xp[2 * c4 + 1], w.y, a1);
                    w = wk2[co * 8 + c4];
                    b0 = fma2(xp[2 * c4], w.x, b0);
                    b1 = fma2(xp[2 * c4 + 1], w.y, b1);
                    w = wv2[co * 8 + c4];
                    c0 = fma2(xp[2 * c4], w.x, c0);
                    c1 = fma2(xp[2 * c4 + 1], w.y, c1);
                }
                qv[j] = hsum(add2(a0, a1)) + bb[co];
                kv[j] = hsum(add2(b0, b1)) + bb[32 + co];
                vv[j] = hsum(add2(c0, c1)) + bb[64 + co];
            }
            float qn = sqrtf(qv[0]*qv[0] + qv[1]*qv[1] + qv[2]*qv[2] + qv[3]*qv[3]);
            float qi = QS / fmaxf(qn, 1e-12f);
            *(float4*)&qbuf[h * 1024 + tok * 4] =
                make_float4(qv[0]*qi, qv[1]*qi, qv[2]*qi, qv[3]*qi);

            float kn = sqrtf(kv[0]*kv[0] + kv[1]*kv[1] + kv[2]*kv[2] + kv[3]*kv[3]);
            float ki = 1.0f / fmaxf(kn, 1e-12f);
            float vn = sqrtf(vv[0]*vv[0] + vv[1]*vv[1] + vv[2]*vv[2] + vv[3]*vv[3]);
            float vi = 1.0f / fmaxf(vn, 1e-12f);

            const int base = h * 1024 + (tok >> 1) * 8 + (tok & 1);
            #pragma unroll
            for (int d = 0; d < 4; d++) {
                kbuf[base + 2 * d] = kv[d] * ki;
                vbuf[base + 2 * d] = vv[d] * vi;
            }
        }
    }
    __syncthreads();

    // =================== Phase A2: attention (1 head / warp) ===============
    ull oa0, oa1, ob0, ob1;                // o pairs for tokens ta, tb
    int ta_, tb_, h2_;
    {
        const int h2 = tid >> 7;           // head 0..7
        const int tp = tid & 127;          // token pair
        const int ta = 2 * tp, tb2 = 2 * tp + 1;
        h2_ = h2; ta_ = ta; tb_ = tb2;

        float4 qa4 = *(const float4*)&qbuf[h2 * 1024 + ta * 4];
        float4 qb4 = *(const float4*)&qbuf[h2 * 1024 + tb2 * 4];
        const ull Qa0 = pk(qa4.x, qa4.x), Qa1 = pk(qa4.y, qa4.y);
        const ull Qa2 = pk(qa4.z, qa4.z), Qa3 = pk(qa4.w, qa4.w);
        const ull Qb0 = pk(qb4.x, qb4.x), Qb1 = pk(qb4.y, qb4.y);
        const ull Qb2 = pk(qb4.z, qb4.z), Qb3 = pk(qb4.w, qb4.w);

        const ulonglong2* kb2 = (const ulonglong2*)(kbuf + h2 * 1024);
        const ulonglong2* vb2 = (const ulonglong2*)(vbuf + h2 * 1024);

        ull paa0 = 0, paa1 = 0, paa2 = 0, paa3 = 0, ssa = 0;
        ull pab0 = 0, pab1 = 0, pab2 = 0, pab3 = 0, ssb = 0;
        #pragma unroll 4
        for (int mp = 0; mp < 128; mp++) {
            ulonglong2 KA = kb2[2 * mp];      // (k0 pair, k1 pair)
            ulonglong2 KB = kb2[2 * mp + 1];  // (k2 pair, k3 pair)
            ull sa = mul2(Qa0, KA.x);
            sa = fma2(Qa1, KA.y, sa);
            sa = fma2(Qa2, KB.x, sa);
            sa = fma2(Qa3, KB.y, sa);
            ull sb = mul2(Qb0, KA.x);
            sb = fma2(Qb1, KA.y, sb);
            sb = fma2(Qb2, KB.x, sb);
            sb = fma2(Qb3, KB.y, sb);
            float sa0, sa1, sb0, sb1;
            upk(sa, sa0, sa1); upk(sb, sb0, sb1);
            ull ppa = pk(ex2f(sa0), ex2f(sa1));
            ull ppb = pk(ex2f(sb0), ex2f(sb1));
            ulonglong2 VA = vb2[2 * mp];
            ulonglong2 VB = vb2[2 * mp + 1];
            ssa = add2(ssa, ppa);
            ssb = add2(ssb, ppb);
            paa0 = fma2(ppa, VA.x, paa0);
            paa1 = fma2(ppa, VA.y, paa1);
            paa2 = fma2(ppa, VB.x, paa2);
            paa3 = fma2(ppa, VB.y, paa3);
            pab0 = fma2(ppb, VA.x, pab0);
            pab1 = fma2(ppb, VA.y, pab1);
            pab2 = fma2(ppb, VB.x, pab2);
            pab3 = fma2(ppb, VB.y, pab3);
        }
        float inva = 1.0f / hsum(ssa);
        float invb = 1.0f / hsum(ssb);
        oa0 = pk(hsum(paa0) * inva, hsum(paa1) * inva);
        oa1 = pk(hsum(paa2) * inva, hsum(paa3) * inva);
        ob0 = pk(hsum(pab0) * invb, hsum(pab1) * invb);
        ob1 = pk(hsum(pab2) * invb, hsum(pab3) * invb);
    }

    // =================== Phase A3: exchange + out projection ===============
    __syncthreads();                       // kbuf/vbuf/qbuf reads done
    {
        ull* osm = (ull*)sm;               // [256 tok][17] ull (16 used)
        osm[ta_ * 17 + 2 * h2_]     = oa0;
        osm[ta_ * 17 + 2 * h2_ + 1] = oa1;
        osm[tb_ * 17 + 2 * h2_]     = ob0;
        osm[tb_ * 17 + 2 * h2_ + 1] = ob1;
        __syncthreads();

        const int tok = tid & 255;
        const int hgg = tid >> 8;
        ull ovv[16];
        #pragma unroll
        for (int i = 0; i < 16; i++) ovv[i] = osm[tok * 17 + i];

        const ull* wmu = (const ull*)wm;
        #pragma unroll
        for (int j = 0; j < 8; j++) {
            const int co = hgg * 8 + j;
            ull a0 = 0, a1 = 0;
            #pragma unroll
            for (int i = 0; i < 16; i += 2) {
                a0 = fma2(ovv[i],     wmu[co * 16 + i],     a0);
                a1 = fma2(ovv[i + 1], wmu[co * 16 + i + 1], a1);
            }
            out[((b * 32 + co) * 9 + t) * 256 + tok] = hsum(add2(a0, a1)) + bb[96 + co];
        }
    }

    gbar(&g_bar1);

    // ======================= Phase B: conv + psums =========================
    {
        float* slab = sm;                  // [288 cikt][32 toks]
        float* cws  = sm + 9216;           // [288 cikt][34]
        ull*   psmem = (ull*)(sm + 19008); // [16 cg][32]
        const int bB = bid >> 3, tq = bid & 7;
        const int tok0 = tq * 32;

        #pragma unroll
        for (int idx = tid; idx < 9216; idx += 1024) {
            int cikt = idx >> 5, ti2 = idx & 31;
            int ci = cikt / 9, kt = cikt - ci * 9;
            float v = (kt < 8) ? out[((bB * 32 + ci) * 9 + kt) * 256 + tok0 + ti2]
                               : pre[ci * 256 + tok0 + ti2];
            slab[idx] = v;
        }
        #pragma unroll
        for (int idx = tid; idx < 9216; idx += 1024) {
            int co = idx / 288, cikt = idx - co * 288;
            cws[cikt * 34 + co] = cw[idx];
        }
        __syncthreads();

        const int w = tid >> 5, lane = tid & 31;
        const int cg = w >> 1, half = w & 1, co = 2 * cg;
        ull acc = (half == 0) ? pk(cb[co], cb[co + 1]) : 0ull;
        const ull* cwsu = (const ull*)cws;
        const int k0 = half * 144;
        #pragma unroll 9
        for (int ckt = k0; ckt < k0 + 144; ckt++) {
            float v = slab[ckt * 32 + lane];
            acc = fma2(pk(v, v), cwsu[ckt * 17 + cg], acc);
        }
        if (half == 1) psmem[cg * 32 + lane] = acc;
        __syncthreads();
        if (half == 0) {
            acc = add2(acc, psmem[cg * 32 + lane]);
            float h0, h1; upk(acc, h0, h1);
            const int gtok = tok0 + lane;
            g_hbuf[(bB * 32 + co) * 256 + gtok]     = h0;
            g_hbuf[(bB * 32 + co + 1) * 256 + gtok] = h1;

            float s0 = h0, q0 = h0 * h0, s1 = h1, q1 = h1 * h1;
            #pragma unroll
            for (int off = 16; off; off >>= 1) {
                s0 += __shfl_down_sync(0xffffffffu, s0, off);
                q0 += __shfl_down_sync(0xffffffffu, q0, off);
                s1 += __shfl_down_sync(0xffffffffu, s1, off);
                q1 += __shfl_down_sync(0xffffffffu, q1, off);
            }
            if (lane == 0) {
                g_psum [co * 128 + bid] = s0;        g_psum2[co * 128 + bid] = q0;
                g_psum [(co + 1) * 128 + bid] = s1;  g_psum2[(co + 1) * 128 + bid] = q1;
            }
        }
    }

    gbar(&g_bar2);

    // ======================= Phase C: BN stats =============================
    {
        float* sred  = sm;           // [32 co][32 part]
        float* sred2 = sm + 1024;
        const int co = tid >> 5, part = tid & 31;
        float s = 0.f, s2 = 0.f;
        #pragma unroll
        for (int i = 0; i < 4; i++) {
            s  += g_psum [co * 128 + part * 4 + i];
            s2 += g_psum2[co * 128 + part * 4 + i];
        }
        sred[co * 32 + part] = s; sred2[co * 32 + part] = s2;
        __syncthreads();
        if (tid < 32) {
            float S = 0.f, S2 = 0.f;
            #pragma unroll
            for (int p = 0; p < 32; p++) { S += sred[tid * 32 + p]; S2 += sred2[tid * 32 + p]; }
            float mean = S * (1.0f / 4096.0f);
            float var = S2 * (1.0f / 4096.0f) - mean * mean;
            float rstd = rsqrtf(var + 1e-5f);
            float sc = rstd * gamma[tid];
            s_sc[tid] = sc;
            s_sh[tid] = beta[tid] - mean * sc;
        }
        __syncthreads();
    }

    // ======================= Phase D: BN+ReLU + linear =====================
    {
        float* hbn = sm;             // [32][256]
        float* lws = sm + 8192;      // [32][260]
        const int lt = bid & 7;
        const int bD = bid >> 3;

        #pragma unroll
        for (int idx = tid; idx < 8192; idx += 1024) {
            int c = idx >> 8;
            float v = g_hbuf[(bD * 32 + c) * 256 + (idx & 255)];
            hbn[idx] = fmaxf(v * s_sc[c] + s_sh[c], 0.f);
        }
        #pragma unroll
        for (int idx = tid; idx < 8192; idx += 1024) {
            int r = idx >> 8, col = idx & 255;
            lws[r * 260 + col] = lw[(lt * 32 + r) * 256 + col];
        }
        __syncthreads();

        const int lane = tid & 31, cq = tid >> 5;   // cq = channel 0..31
        ull acc0 = 0;
        const ulonglong2* wrow = (const ulonglong2*)&lws[lane * 260];
        const ulonglong2* h0 = (const ulonglong2*)&hbn[cq * 256];
        #pragma unroll 8
        for (int l4 = 0; l4 < 64; l4++) {
            ulonglong2 w = wrow[l4];
            ulonglong2 a = h0[l4];
            acc0 = fma2(w.x, a.x, acc0);
            acc0 = fma2(w.y, a.y, acc0);
        }

        const int lp = lt * 32 + lane;
        float p = hsum(acc0) + lb[lp];
        int base = (bD * 32 + cq) * 9;
        out[(base + 8) * 256 + lp] = out[(base + 2) * 256 + lp] - p;
    }

    // ---- epilogue: last block resets barrier counters for next launch ----
    __syncthreads();
    if (tid == 0) {
        unsigned old = atomicAdd(&g_fin, 1u);
        if (old == 127u) {
            atomicExch(&g_bar1, 0u);
            atomicExch(&g_bar2, 0u);
            atomicExch(&g_fin, 0u);
        }
    }
}

// ---------------------------------------------------------------------------
extern "C" void kernel_launch(void* const* d_in, const int* in_sizes, int n_in,
                              void* d_out, int out_size)
{
    const float* x     = (const float*)d_in[0];
    const float* qw    = (const float*)d_in[1];
    const float* qb    = (const float*)d_in[2];
    const float* kw    = (const float*)d_in[3];
    const float* kb    = (const float*)d_in[4];
    const float* vw    = (const float*)d_in[5];
    const float* vb    = (const float*)d_in[6];
    const float* mw    = (const float*)d_in[7];
    const float* mb    = (const float*)d_in[8];
    const float* pre   = (const float*)d_in[9];
    const float* cw    = (const float*)d_in[10];
    const float* cb    = (const float*)d_in[11];
    const float* gamma = (const float*)d_in[12];
    const float* beta  = (const float*)d_in[13];
    const float* lw    = (const float*)d_in[14];
    const float* lb    = (const float*)d_in[15];
    float* out = (float*)d_out;

    const int smem = (8192 + 8192 + 8192 + 4096 + 128) * 4;   // 115200 B
    cudaFuncSetAttribute(k_fused, cudaFuncAttributeMaxDynamicSharedMemorySize, smem);

    k_fused<<<128, 1024, smem>>>(x, qw, qb, kw, kb, vw, vb, mw, mb,
                                 pre, cw, cb, gamma, beta, lw, lb, out);
}